// round 1
// baseline (speedup 1.0000x reference)
#include <cuda_runtime.h>
#include <math.h>

// Problem shape (fixed by the dataset)
#define T_DIM 2048
#define N_DIM 64
#define D_DIM 1024

#define EPS 1e-6f
#define HALF_LOG_2PI 0.9189385332046727f

__global__ void zero_out_kernel(float* __restrict__ out, int n) {
    int i = blockIdx.x * blockDim.x + threadIdx.x;
    if (i < n) out[i] = 0.0f;
}

// One block per (t, n) row of x. 256 threads * float4 = 1024 = D.
__global__ __launch_bounds__(256, 8)
void gaussian_nll_kernel(const float* __restrict__ y,
                         const float* __restrict__ x,
                         const float* __restrict__ W,
                         const int* __restrict__ lens,
                         float* __restrict__ out) {
    const int t = blockIdx.x;
    const int n = blockIdx.y;

    // Skip invalid positions entirely: no x traffic for masked rows.
    if (t >= __ldg(&lens[n])) return;

    const int tid = threadIdx.x;

    const float4* xr = reinterpret_cast<const float4*>(
        x + ((size_t)t * N_DIM + n) * D_DIM);
    const float4* w0 = reinterpret_cast<const float4*>(W);          // W[0,:]
    const float4* w1 = reinterpret_cast<const float4*>(W + D_DIM);  // W[1,:]

    float4 xv = xr[tid];
    float4 a  = __ldg(&w0[tid]);
    float4 b  = __ldg(&w1[tid]);

    float d0 = fmaf(xv.x, a.x, fmaf(xv.y, a.y, fmaf(xv.z, a.z, xv.w * a.w)));
    float d1 = fmaf(xv.x, b.x, fmaf(xv.y, b.y, fmaf(xv.z, b.z, xv.w * b.w)));

    // Warp reduction
    #pragma unroll
    for (int off = 16; off > 0; off >>= 1) {
        d0 += __shfl_down_sync(0xFFFFFFFFu, d0, off);
        d1 += __shfl_down_sync(0xFFFFFFFFu, d1, off);
    }

    __shared__ float s0[8], s1[8];
    const int warp = tid >> 5;
    if ((tid & 31) == 0) { s0[warp] = d0; s1[warp] = d1; }
    __syncthreads();

    if (warp == 0) {
        d0 = (tid < 8) ? s0[tid] : 0.0f;
        d1 = (tid < 8) ? s1[tid] : 0.0f;
        #pragma unroll
        for (int off = 4; off > 0; off >>= 1) {
            d0 += __shfl_down_sync(0xFFFFFFFFu, d0, off);
            d1 += __shfl_down_sync(0xFFFFFFFFu, d1, off);
        }
        if (tid == 0) {
            const float mu = d0;
            const float z  = d1;
            float var = 1.0f / (1.0f + expf(-z));   // sigmoid
            var = fmaxf(var, EPS);
            const float yy = __ldg(&y[(size_t)t * N_DIM + n]);
            const float dy = yy - mu;
            const float nll = 0.5f * (logf(var) + dy * dy / var) + HALF_LOG_2PI;
            atomicAdd(&out[n], nll);
        }
    }
}

extern "C" void kernel_launch(void* const* d_in, const int* in_sizes, int n_in,
                              void* d_out, int out_size) {
    const float* y    = (const float*)d_in[0];   // (T, N)
    const float* x    = (const float*)d_in[1];   // (T, N, D)
    const float* W    = (const float*)d_in[2];   // (2, D)
    const int*   lens = (const int*)d_in[3];     // (N,)
    float* out = (float*)d_out;                  // (N,)

    zero_out_kernel<<<1, 64>>>(out, out_size);

    dim3 grid(T_DIM, N_DIM);
    gaussian_nll_kernel<<<grid, 256>>>(y, x, W, lens, out);
}

// round 5
// speedup vs baseline: 2.1067x; 2.1067x over previous
#include <cuda_runtime.h>
#include <math.h>

// Problem shape (fixed by the dataset)
#define T_DIM 2048
#define N_DIM 64
#define D_DIM 1024

#define ROWS_PER_BLOCK 8   // one row per warp, 8 warps per block

#define EPS 1e-6f
#define HALF_LOG_2PI 0.9189385332046727f

__global__ void zero_out_kernel(float* __restrict__ out, int n) {
    int i = blockIdx.x * blockDim.x + threadIdx.x;
    if (i < n) out[i] = 0.0f;
}

// Warp-per-row: each warp streams a full D=1024 row (8 x LDG.128 per lane,
// independent -> MLP~8), then ONE shuffle reduction per row. Block gathers
// its 8 row-NLLs and issues one atomic per block.
// launch_bounds(256,4): 64 regs/thread budget so the 8-deep load batch
// stays in registers (no local-memory spills).
__global__ __launch_bounds__(256, 4)
void gaussian_nll_kernel(const float* __restrict__ y,
                         const float* __restrict__ x,
                         const float* __restrict__ W,
                         const int* __restrict__ lens,
                         float* __restrict__ out) {
    const int n   = blockIdx.y;
    const int len = __ldg(&lens[n]);
    const int t0  = blockIdx.x * ROWS_PER_BLOCK;

    // Whole block past this sequence's length: zero traffic.
    // (t0, len uniform across block -> no divergent-sync hazard.)
    if (t0 >= len) return;

    const int warp = threadIdx.x >> 5;
    const int lane = threadIdx.x & 31;
    const int t    = t0 + warp;

    float nll = 0.0f;

    if (t < len) {
        const float4* __restrict__ xr =
            reinterpret_cast<const float4*>(x + ((size_t)t * N_DIM + n) * D_DIM);
        const float4* __restrict__ w0 = reinterpret_cast<const float4*>(W);
        const float4* __restrict__ w1 = reinterpret_cast<const float4*>(W + D_DIM);

        // Front-batch the 8 independent x-row loads (DRAM, MLP_p1=8).
        float4 xv[8];
        #pragma unroll
        for (int i = 0; i < 8; i++) xv[i] = xr[i * 32 + lane];

        // W loads are L1/L2 hits (8 KB, shared by every block); consume xv
        // as we go so live-register pressure stays within the 64-reg budget.
        float d0 = 0.0f, d1 = 0.0f;
        #pragma unroll
        for (int i = 0; i < 8; i++) {
            const int idx = i * 32 + lane;
            float4 a = __ldg(&w0[idx]);
            float4 b = __ldg(&w1[idx]);
            d0 = fmaf(xv[i].x, a.x, fmaf(xv[i].y, a.y,
                 fmaf(xv[i].z, a.z, fmaf(xv[i].w, a.w, d0))));
            d1 = fmaf(xv[i].x, b.x, fmaf(xv[i].y, b.y,
                 fmaf(xv[i].z, b.z, fmaf(xv[i].w, b.w, d1))));
        }

        // Single warp reduction for both dots
        #pragma unroll
        for (int off = 16; off > 0; off >>= 1) {
            d0 += __shfl_down_sync(0xFFFFFFFFu, d0, off);
            d1 += __shfl_down_sync(0xFFFFFFFFu, d1, off);
        }

        if (lane == 0) {
            const float mu = d0;
            float var = 1.0f / (1.0f + __expf(-d1));  // sigmoid
            var = fmaxf(var, EPS);
            const float yy = __ldg(&y[(size_t)t * N_DIM + n]);
            const float dy = yy - mu;
            nll = 0.5f * (logf(var) + dy * dy / var) + HALF_LOG_2PI;
        }
    }

    // Gather the block's 8 row-NLLs -> one atomic per block (256 per out[n]).
    __shared__ float s[ROWS_PER_BLOCK];
    if (lane == 0) s[warp] = nll;     // invalid warps contribute 0
    __syncthreads();

    if (threadIdx.x == 0) {
        float sum = 0.0f;
        #pragma unroll
        for (int i = 0; i < ROWS_PER_BLOCK; i++) sum += s[i];
        atomicAdd(&out[n], sum);
    }
}

extern "C" void kernel_launch(void* const* d_in, const int* in_sizes, int n_in,
                              void* d_out, int out_size) {
    const float* y    = (const float*)d_in[0];   // (T, N)
    const float* x    = (const float*)d_in[1];   // (T, N, D)
    const float* W    = (const float*)d_in[2];   // (2, D)
    const int*   lens = (const int*)d_in[3];     // (N,)
    float* out = (float*)d_out;                  // (N,)

    zero_out_kernel<<<1, 64>>>(out, out_size);

    dim3 grid(T_DIM / ROWS_PER_BLOCK, N_DIM);
    gaussian_nll_kernel<<<grid, 256>>>(y, x, W, lens, out);
}

// round 6
// speedup vs baseline: 2.2611x; 1.0733x over previous
#include <cuda_runtime.h>
#include <math.h>

// Problem shape (fixed by the dataset)
#define T_DIM 2048
#define N_DIM 64
#define D_DIM 1024

#define WPB 8                   // warps per block
#define BX  32                  // grid.x
#define WSTRIDE (WPB * BX)      // 256 warps striding over t per sequence

#define EPS 1e-6f
#define LOG_EPS -13.8155106f    // log(1e-6)
#define Z_CLAMP -13.8155121f    // log(eps/(1-eps)): sigmoid(z) < eps below this
#define HALF_LOG_2PI 0.9189385332046727f

__global__ void zero_out_kernel(float* __restrict__ out, int n) {
    int i = blockIdx.x * blockDim.x + threadIdx.x;
    if (i < n) out[i] = 0.0f;
}

// Persistent warp: each warp owns rows t = wg, wg+256, ... of sequence n
// (<= 8 rows). The ENTIRE next row is prefetched (8 independent LDG.128)
// before the current row's FMA/shfl/MUFU tail, so the warp never
// compute-stalls on DRAM and the LSU streams continuously.
// No shared memory, no __syncthreads; one atomic per warp.
__global__ __launch_bounds__(256, 2)
void gaussian_nll_kernel(const float* __restrict__ y,
                         const float* __restrict__ x,
                         const float* __restrict__ W,
                         const int* __restrict__ lens,
                         float* __restrict__ out) {
    const int n    = blockIdx.y;
    const int len  = __ldg(&lens[n]);
    const int warp = threadIdx.x >> 5;
    const int lane = threadIdx.x & 31;
    const int wg   = blockIdx.x * WPB + warp;   // 0..255: first row this warp owns

    if (wg >= len) return;   // warp-uniform; no block-level sync exists below

    const float4* __restrict__ w0 = reinterpret_cast<const float4*>(W);
    const float4* __restrict__ w1 = reinterpret_cast<const float4*>(W + D_DIM);

    float nll_sum = 0.0f;    // meaningful on lane 0 only
    int t = wg;

    // Prime: load first row
    float4 cur[8];
    {
        const float4* __restrict__ xr =
            reinterpret_cast<const float4*>(x + ((size_t)t * N_DIM + n) * D_DIM);
        #pragma unroll
        for (int i = 0; i < 8; i++) cur[i] = xr[i * 32 + lane];
    }
    float ycur = __ldg(&y[(size_t)t * N_DIM + n]);

    while (true) {
        // ---- Prefetch next row (in flight during current row's compute) ----
        const int  tn        = t + WSTRIDE;
        const bool have_next = tn < len;
        float4 nxt[8];
        float  ynxt = 0.0f;
        if (have_next) {
            const float4* __restrict__ xrn =
                reinterpret_cast<const float4*>(x + ((size_t)tn * N_DIM + n) * D_DIM);
            #pragma unroll
            for (int i = 0; i < 8; i++) nxt[i] = xrn[i * 32 + lane];
            ynxt = __ldg(&y[(size_t)tn * N_DIM + n]);
        }

        // ---- Compute current row: two dots, dual accumulators ----
        float d0a = 0.0f, d0b = 0.0f, d1a = 0.0f, d1b = 0.0f;
        #pragma unroll
        for (int i = 0; i < 8; i += 2) {
            const int i0 = i * 32 + lane, i1 = (i + 1) * 32 + lane;
            float4 a0 = __ldg(&w0[i0]), b0 = __ldg(&w1[i0]);   // L1 hits (8 KB)
            float4 a1 = __ldg(&w0[i1]), b1 = __ldg(&w1[i1]);
            d0a = fmaf(cur[i].x, a0.x, fmaf(cur[i].y, a0.y,
                  fmaf(cur[i].z, a0.z, fmaf(cur[i].w, a0.w, d0a))));
            d1a = fmaf(cur[i].x, b0.x, fmaf(cur[i].y, b0.y,
                  fmaf(cur[i].z, b0.z, fmaf(cur[i].w, b0.w, d1a))));
            d0b = fmaf(cur[i+1].x, a1.x, fmaf(cur[i+1].y, a1.y,
                  fmaf(cur[i+1].z, a1.z, fmaf(cur[i+1].w, a1.w, d0b))));
            d1b = fmaf(cur[i+1].x, b1.x, fmaf(cur[i+1].y, b1.y,
                  fmaf(cur[i+1].z, b1.z, fmaf(cur[i+1].w, b1.w, d1b))));
        }
        float d0 = d0a + d0b, d1 = d1a + d1b;

        #pragma unroll
        for (int off = 16; off > 0; off >>= 1) {
            d0 += __shfl_down_sync(0xFFFFFFFFu, d0, off);
            d1 += __shfl_down_sync(0xFFFFFFFFu, d1, off);
        }

        if (lane == 0) {
            // var = max(sigmoid(z), eps); use 1/var = 1 + e^{-z},
            // log var = -log(1 + e^{-z}) -- one exp + one log, no division.
            const float z = d1;
            float logv, inv_v;
            if (z > Z_CLAMP) {
                const float e = __expf(-z);
                inv_v = 1.0f + e;
                logv  = -__logf(inv_v);
            } else {
                inv_v = 1.0f / EPS;
                logv  = LOG_EPS;
            }
            const float dy = ycur - d0;
            nll_sum += 0.5f * (logv + dy * dy * inv_v) + HALF_LOG_2PI;
        }

        if (!have_next) break;
        #pragma unroll
        for (int i = 0; i < 8; i++) cur[i] = nxt[i];   // register rotate
        ycur = ynxt;
        t = tn;
    }

    if (lane == 0) atomicAdd(&out[n], nll_sum);
}

extern "C" void kernel_launch(void* const* d_in, const int* in_sizes, int n_in,
                              void* d_out, int out_size) {
    const float* y    = (const float*)d_in[0];   // (T, N)
    const float* x    = (const float*)d_in[1];   // (T, N, D)
    const float* W    = (const float*)d_in[2];   // (2, D)
    const int*   lens = (const int*)d_in[3];     // (N,)
    float* out = (float*)d_out;                  // (N,)

    zero_out_kernel<<<1, 64>>>(out, out_size);

    dim3 grid(BX, N_DIM);
    gaussian_nll_kernel<<<grid, 256>>>(y, x, W, lens, out);
}